// round 4
// baseline (speedup 1.0000x reference)
#include <cuda_runtime.h>
#include <math.h>

#define N_PTS 16384            // 2*8192 points, both batches flattened
#define KNN 5
#define NC 64                  // cells per axis
#define NCELLS (NC * NC)       // 4096
#define XMIN (-4.5f)
#define W (9.0f / NC)          // 0.140625
#define INV_W (NC / 9.0f)

#define MAIN_THREADS 256
#define MAIN_WARPS (MAIN_THREADS / 32)            // 8
#define SRC_PER_WARP 4
#define SRC_PER_BLOCK (MAIN_WARPS * SRC_PER_WARP) // 32
#define MAIN_BLOCKS (N_PTS / SRC_PER_BLOCK)       // 512

// ---- scratch (zero-initialized at module load; finalize re-zeroes hists) ----
__device__ float4 g_tsort[N_PTS];   // (-2x,-2y,-2z,t^2) cell-ordered; invalid w=1e30
__device__ float4 g_ssort[N_PTS];   // (x,y,z, valid? s2 : -1) cell-ordered
__device__ int    g_thist[NCELLS];
__device__ int    g_shist[NCELLS];
__device__ int    g_tstart[NCELLS + 1];
__device__ int    g_sstart[NCELLS + 1];
__device__ int    g_tcur[NCELLS];
__device__ int    g_scur[NCELLS];
__device__ float  g_bsum[MAIN_BLOCKS];
__device__ int    g_bcnt[MAIN_BLOCKS];

__device__ __forceinline__ int cell_coord(float v) {
    int c = (int)floorf((v - XMIN) * INV_W);
    return min(NC - 1, max(0, c));
}

// ---------------------------------------------------------------------------
// hist: 2D cell histogram for both clouds (hists pre-zeroed by finalize/load)
// ---------------------------------------------------------------------------
__global__ void hist_kernel(const float* __restrict__ src,
                            const float* __restrict__ tgt) {
    int gid = blockIdx.x * blockDim.x + threadIdx.x;   // 0..32767
    if (gid < N_PTS) {
        int c = cell_coord(tgt[3 * gid + 1]) * NC + cell_coord(tgt[3 * gid]);
        atomicAdd(&g_thist[c], 1);
    } else {
        int i = gid - N_PTS;
        int c = cell_coord(src[3 * i + 1]) * NC + cell_coord(src[3 * i]);
        atomicAdd(&g_shist[c], 1);
    }
}

// ---------------------------------------------------------------------------
// scan: exclusive scan of both 4096-cell histograms. 1 block, 1024 threads,
// 4 cells per thread, Hillis-Steele over per-thread partials.
// ---------------------------------------------------------------------------
__global__ void scan_kernel() {
    __shared__ int pt[1024], ps[1024];
    const int tid = threadIdx.x;
    int tl[4], sl[4], tsum = 0, ssum = 0;
#pragma unroll
    for (int j = 0; j < 4; ++j) {
        tl[j] = g_thist[tid * 4 + j];  tsum += tl[j];
        sl[j] = g_shist[tid * 4 + j];  ssum += sl[j];
    }
    pt[tid] = tsum; ps[tid] = ssum;
    __syncthreads();
    for (int off = 1; off < 1024; off <<= 1) {
        int ta = (tid >= off) ? pt[tid - off] : 0;
        int sa = (tid >= off) ? ps[tid - off] : 0;
        __syncthreads();
        pt[tid] += ta; ps[tid] += sa;
        __syncthreads();
    }
    int trun = pt[tid] - tsum;   // exclusive offsets
    int srun = ps[tid] - ssum;
#pragma unroll
    for (int j = 0; j < 4; ++j) {
        int c = tid * 4 + j;
        g_tstart[c] = trun; g_tcur[c] = trun; trun += tl[j];
        g_sstart[c] = srun; g_scur[c] = srun; srun += sl[j];
    }
    if (tid == 1023) { g_tstart[NCELLS] = N_PTS; g_sstart[NCELLS] = N_PTS; }
}

// ---------------------------------------------------------------------------
// scatter into cell order, transforming on the way
// ---------------------------------------------------------------------------
__global__ void scatter_kernel(const float* __restrict__ src,
                               const float* __restrict__ tgt) {
    int gid = blockIdx.x * blockDim.x + threadIdx.x;
    if (gid < N_PTS) {
        float x = tgt[3 * gid], y = tgt[3 * gid + 1], z = tgt[3 * gid + 2];
        bool valid = (x != 0.0f) || (y != 0.0f) || (z != 0.0f);
        float t2 = fmaf(x, x, fmaf(y, y, z * z));
        float4 v;
        if (valid) { v.x = -2.0f * x; v.y = -2.0f * y; v.z = -2.0f * z; v.w = t2; }
        else       { v.x = 0.0f;      v.y = 0.0f;      v.z = 0.0f;      v.w = 1e30f; }
        int c = cell_coord(y) * NC + cell_coord(x);
        g_tsort[atomicAdd(&g_tcur[c], 1)] = v;
    } else {
        int i = gid - N_PTS;
        float x = src[3 * i], y = src[3 * i + 1], z = src[3 * i + 2];
        bool valid = (x != 0.0f) || (y != 0.0f) || (z != 0.0f);
        float s2 = fmaf(x, x, fmaf(y, y, z * z));
        float4 v; v.x = x; v.y = y; v.z = z; v.w = valid ? s2 : -1.0f;
        int c = cell_coord(y) * NC + cell_coord(x);
        g_ssort[atomicAdd(&g_scur[c], 1)] = v;
    }
}

// Branchless sorted insert, ascending m0..m4 (exact no-op when q >= m4).
__device__ __forceinline__ void insert5(float q, float& m0, float& m1,
                                        float& m2, float& m3, float& m4) {
    float t0 = fminf(m0, q);
    float t1 = fminf(m1, fmaxf(m0, q));
    float t2 = fminf(m2, fmaxf(m1, q));
    float t3 = fminf(m3, fmaxf(m2, q));
    float t4 = fminf(m4, fmaxf(m3, q));
    m0 = t0; m1 = t1; m2 = t2; m3 = t3; m4 = t4;
}

// ---------------------------------------------------------------------------
// Main: warp owns 4 cell-adjacent sources. Each LANE keeps its own top-5
// (branchless unconditional insert) over lane-strided candidates; lists
// merged across lanes at the end via shfl butterfly + bitonic lower-half.
// Target cells visited as expanding square rings with exact rect bounds.
// ---------------------------------------------------------------------------
__global__ __launch_bounds__(MAIN_THREADS)
void knn_main() {
    __shared__ float red_s[MAIN_WARPS];
    __shared__ int   red_c[MAIN_WARPS];

    const int lane = threadIdx.x & 31;
    const int warp = threadIdx.x >> 5;
    const int sbase = (blockIdx.x * MAIN_WARPS + warp) * SRC_PER_WARP;

    float sx[SRC_PER_WARP], sy[SRC_PER_WARP], sz[SRC_PER_WARP], s2v[SRC_PER_WARP];
    bool  sval[SRC_PER_WARP];
    float xlo = 1e30f, xhi = -1e30f, ylo = 1e30f, yhi = -1e30f;
    bool any_valid = false;
#pragma unroll
    for (int s = 0; s < SRC_PER_WARP; ++s) {
        float4 v = g_ssort[sbase + s];
        sx[s] = v.x; sy[s] = v.y; sz[s] = v.z;
        sval[s] = (v.w >= 0.0f);
        s2v[s]  = fmaxf(v.w, 0.0f);
        if (sval[s]) {
            any_valid = true;
            xlo = fminf(xlo, v.x); xhi = fmaxf(xhi, v.x);
            ylo = fminf(ylo, v.y); yhi = fmaxf(yhi, v.y);
        }
    }

    float m[SRC_PER_WARP][KNN];
#pragma unroll
    for (int s = 0; s < SRC_PER_WARP; ++s)
#pragma unroll
        for (int k = 0; k < KNN; ++k) m[s][k] = 1e20f;

    if (any_valid) {
        // clamp bbox into grid domain (conservative for pruning bounds)
        float cxlo = fminf(fmaxf(xlo, XMIN), XMIN + NC * W);
        float cxhi = fminf(fmaxf(xhi, XMIN), XMIN + NC * W);
        float cylo = fminf(fmaxf(ylo, XMIN), XMIN + NC * W);
        float cyhi = fminf(fmaxf(yhi, XMIN), XMIN + NC * W);

        const int cx0 = cell_coord(cxlo), cx1 = cell_coord(cxhi);
        const int cy0 = cell_coord(cylo), cy1 = cell_coord(cyhi);

        float r2 = 1e30f;   // current pruning bound (squared distance)

        // process one contiguous span of cells in row cy: [cxl, cxr]
        auto process_span = [&](int cy, int cxl, int cxr) {
            cxl = max(cxl, 0); cxr = min(cxr, NC - 1);
            if (cxl > cxr) return;
            int st = g_tstart[cy * NC + cxl];
            int en = g_tstart[cy * NC + cxr + 1];
            for (int i0 = st; i0 < en; i0 += 32) {
                int i = i0 + lane;
                float4 v = make_float4(0.0f, 0.0f, 0.0f, 1e30f);
                if (i < en) v = g_tsort[i];
#pragma unroll
                for (int s = 0; s < SRC_PER_WARP; ++s) {
                    float q = fmaf(sx[s], v.x,
                              fmaf(sy[s], v.y,
                              fmaf(sz[s], v.z, v.w)));
                    insert5(q, m[s][0], m[s][1], m[s][2], m[s][3], m[s][4]);
                }
            }
        };

        // home rect
        for (int cy = cy0; cy <= cy1; ++cy) process_span(cy, cx0, cx1);

        for (int rho = 1; rho < NC; ++rho) {
            // refresh pruning bound: global 5th <= min over lanes of lane 5th
            float nr2 = 0.0f;
#pragma unroll
            for (int s = 0; s < SRC_PER_WARP; ++s) {
                float mv = m[s][4];
#pragma unroll
                for (int off = 16; off > 0; off >>= 1)
                    mv = fminf(mv, __shfl_xor_sync(0xffffffffu, mv, off));
                if (sval[s]) nr2 = fmaxf(nr2, mv + s2v[s]);
            }
            r2 = nr2;

            float lbr = (rho - 1) * W;
            if (lbr * lbr > r2) break;

            const int nx0 = cx0 - rho, nx1 = cx1 + rho;
            const int ny0 = cy0 - rho, ny1 = cy1 + rho;

            // top / bottom rows (contiguous spans), with row y-bound check
            if (ny0 >= 0) {
                float dy = fmaxf(cylo - (XMIN + (ny0 + 1) * W), 0.0f);
                if (dy * dy <= r2) process_span(ny0, nx0, nx1);
            }
            if (ny1 <= NC - 1) {
                float dy = fmaxf((XMIN + ny1 * W) - cyhi, 0.0f);
                if (dy * dy <= r2) process_span(ny1, nx0, nx1);
            }
            // left / right columns (per-cell), rows [ny0+1, ny1-1]
            int ra = max(ny0 + 1, 0), rb = min(ny1 - 1, NC - 1);
            if (nx0 >= 0) {
                float dx = fmaxf(cxlo - (XMIN + (nx0 + 1) * W), 0.0f);
                if (dx * dx <= r2) {
                    for (int r = ra; r <= rb; ++r) {
                        float cymin = XMIN + r * W;
                        float dy = fmaxf(fmaxf(cymin - cyhi, cylo - (cymin + W)), 0.0f);
                        if (fmaf(dy, dy, dx * dx) <= r2) process_span(r, nx0, nx0);
                    }
                }
            }
            if (nx1 <= NC - 1) {
                float dx = fmaxf((XMIN + nx1 * W) - cxhi, 0.0f);
                if (dx * dx <= r2) {
                    for (int r = ra; r <= rb; ++r) {
                        float cymin = XMIN + r * W;
                        float dy = fmaxf(fmaxf(cymin - cyhi, cylo - (cymin + W)), 0.0f);
                        if (fmaf(dy, dy, dx * dx) <= r2) process_span(r, nx1, nx1);
                    }
                }
            }
            if (nx0 <= 0 && nx1 >= NC - 1 && ny0 <= 0 && ny1 >= NC - 1) break;
        }
    }

    // merge 32 per-lane sorted-5 lists -> global sorted-5 (identical on lanes)
    float wsum = 0.0f; int wcnt = 0;
#pragma unroll
    for (int s = 0; s < SRC_PER_WARP; ++s) {
        float a0 = m[s][0], a1 = m[s][1], a2 = m[s][2], a3 = m[s][3], a4 = m[s][4];
#pragma unroll
        for (int off = 16; off > 0; off >>= 1) {
            float b0 = __shfl_xor_sync(0xffffffffu, a0, off);
            float b1 = __shfl_xor_sync(0xffffffffu, a1, off);
            float b2 = __shfl_xor_sync(0xffffffffu, a2, off);
            float b3 = __shfl_xor_sync(0xffffffffu, a3, off);
            float b4 = __shfl_xor_sync(0xffffffffu, a4, off);
            // bitonic lower half: smallest-5 multiset of the union
            float c0 = fminf(a0, b4), c1 = fminf(a1, b3), c2 = fminf(a2, b2);
            float c3 = fminf(a3, b1), c4 = fminf(a4, b0);
            // sort the bitonic 5-sequence (5 compare-exchanges)
            float l04 = fminf(c0, c4), h04 = fmaxf(c0, c4);
            float l13 = fminf(c1, c3), h13 = fmaxf(c1, c3);
            float l2h = fminf(c2, h04), h2h = fmaxf(c2, h04);
            a0 = l04;
            a1 = fminf(l13, l2h); a2 = fmaxf(l13, l2h);
            a3 = fminf(h13, h2h); a4 = fmaxf(h13, h2h);
        }
        float acc = sqrtf(fmaxf(a0 + s2v[s], 1e-12f))
                  + sqrtf(fmaxf(a1 + s2v[s], 1e-12f))
                  + sqrtf(fmaxf(a2 + s2v[s], 1e-12f))
                  + sqrtf(fmaxf(a3 + s2v[s], 1e-12f))
                  + sqrtf(fmaxf(a4 + s2v[s], 1e-12f));
        if (sval[s]) { wsum += acc; wcnt += 1; }
    }

    if (lane == 0) { red_s[warp] = wsum; red_c[warp] = wcnt; }
    __syncthreads();
    if (threadIdx.x == 0) {
        float bs = 0.0f; int bc = 0;
#pragma unroll
        for (int w = 0; w < MAIN_WARPS; ++w) { bs += red_s[w]; bc += red_c[w]; }
        g_bsum[blockIdx.x] = bs;
        g_bcnt[blockIdx.x] = bc;
    }
}

// ---------------------------------------------------------------------------
// finalize: reduce 512 partials in double, write scalar, re-zero histograms
// for the next call (first call uses load-time zero-init).
// ---------------------------------------------------------------------------
__global__ void finalize_kernel(float* __restrict__ out) {
    __shared__ double ds[256];
    __shared__ int    di[256];
    int tid = threadIdx.x;
    double s = 0.0; int c = 0;
    for (int i = tid; i < MAIN_BLOCKS; i += 256) { s += (double)g_bsum[i]; c += g_bcnt[i]; }
    ds[tid] = s; di[tid] = c;
    __syncthreads();
#pragma unroll
    for (int off = 128; off > 0; off >>= 1) {
        if (tid < off) { ds[tid] += ds[tid + off]; di[tid] += di[tid + off]; }
        __syncthreads();
    }
    if (tid == 0) out[0] = (float)(ds[0] / ((double)di[0] * KNN));
    // re-zero histograms for next call
    for (int i = tid; i < NCELLS; i += 256) { g_thist[i] = 0; g_shist[i] = 0; }
}

// ---------------------------------------------------------------------------
extern "C" void kernel_launch(void* const* d_in, const int* in_sizes, int n_in,
                              void* d_out, int out_size) {
    const float* src = (const float*)d_in[0];  // source_pc (2,8192,3)
    const float* tgt = (const float*)d_in[1];  // target_pc (2,8192,3)
    float* out = (float*)d_out;

    hist_kernel<<<2 * N_PTS / 256, 256>>>(src, tgt);     // launch 0
    scan_kernel<<<1, 1024>>>();                          // launch 1
    scatter_kernel<<<2 * N_PTS / 256, 256>>>(src, tgt);  // launch 2
    knn_main<<<MAIN_BLOCKS, MAIN_THREADS>>>();           // launch 3 (profiled)
    finalize_kernel<<<1, 256>>>(out);                    // launch 4
}

// round 5
// speedup vs baseline: 1.0213x; 1.0213x over previous
#include <cuda_runtime.h>
#include <math.h>

#define N_PTS 16384            // 2*8192 points, both batches flattened
#define KNN 5
#define NC 80                  // cells per axis
#define NCELLS (NC * NC)       // 6400
#define XMIN (-4.5f)
#define W (9.0f / NC)          // 0.1125
#define INV_W (NC / 9.0f)

#define MAIN_THREADS 128
#define MAIN_WARPS (MAIN_THREADS / 32)            // 4
#define SRC_PER_WARP 4
#define SRC_PER_BLOCK (MAIN_WARPS * SRC_PER_WARP) // 16
#define MAIN_BLOCKS (N_PTS / SRC_PER_BLOCK)       // 1024

// ---- scratch (zero-initialized at module load; finalize re-zeroes hists) ----
__device__ float4 g_tsort[N_PTS];   // (-2x,-2y,-2z,t^2) cell-ordered; invalid w=1e30
__device__ float4 g_ssort[N_PTS];   // (x,y,z, valid? s2 : -1) cell-ordered
__device__ int    g_thist[NCELLS];
__device__ int    g_shist[NCELLS];
__device__ int    g_tstart[NCELLS + 1];
__device__ int    g_sstart[NCELLS + 1];
__device__ int    g_tcur[NCELLS];
__device__ int    g_scur[NCELLS];
__device__ float  g_bsum[MAIN_BLOCKS];
__device__ int    g_bcnt[MAIN_BLOCKS];

__device__ __forceinline__ int cell_coord(float v) {
    int c = (int)floorf((v - XMIN) * INV_W);
    return min(NC - 1, max(0, c));
}

// ---------------------------------------------------------------------------
__global__ void hist_kernel(const float* __restrict__ src,
                            const float* __restrict__ tgt) {
    int gid = blockIdx.x * blockDim.x + threadIdx.x;   // 0..32767
    if (gid < N_PTS) {
        int c = cell_coord(tgt[3 * gid + 1]) * NC + cell_coord(tgt[3 * gid]);
        atomicAdd(&g_thist[c], 1);
    } else {
        int i = gid - N_PTS;
        int c = cell_coord(src[3 * i + 1]) * NC + cell_coord(src[3 * i]);
        atomicAdd(&g_shist[c], 1);
    }
}

// ---------------------------------------------------------------------------
// scan: exclusive scan of both 6400-cell histograms. 1 block, 1024 threads,
// 7 cells per thread (guarded), Hillis-Steele over per-thread partials.
// ---------------------------------------------------------------------------
#define CELLS_PER_T 7
__global__ void scan_kernel() {
    __shared__ int pt[1024], ps[1024];
    const int tid = threadIdx.x;
    int tl[CELLS_PER_T], sl[CELLS_PER_T], tsum = 0, ssum = 0;
#pragma unroll
    for (int j = 0; j < CELLS_PER_T; ++j) {
        int c = tid * CELLS_PER_T + j;
        tl[j] = (c < NCELLS) ? g_thist[c] : 0;  tsum += tl[j];
        sl[j] = (c < NCELLS) ? g_shist[c] : 0;  ssum += sl[j];
    }
    pt[tid] = tsum; ps[tid] = ssum;
    __syncthreads();
    for (int off = 1; off < 1024; off <<= 1) {
        int ta = (tid >= off) ? pt[tid - off] : 0;
        int sa = (tid >= off) ? ps[tid - off] : 0;
        __syncthreads();
        pt[tid] += ta; ps[tid] += sa;
        __syncthreads();
    }
    int trun = pt[tid] - tsum;   // exclusive offsets
    int srun = ps[tid] - ssum;
#pragma unroll
    for (int j = 0; j < CELLS_PER_T; ++j) {
        int c = tid * CELLS_PER_T + j;
        if (c < NCELLS) {
            g_tstart[c] = trun; g_tcur[c] = trun; trun += tl[j];
            g_sstart[c] = srun; g_scur[c] = srun; srun += sl[j];
        }
    }
    if (tid == 1023) { g_tstart[NCELLS] = N_PTS; g_sstart[NCELLS] = N_PTS; }
}

// ---------------------------------------------------------------------------
__global__ void scatter_kernel(const float* __restrict__ src,
                               const float* __restrict__ tgt) {
    int gid = blockIdx.x * blockDim.x + threadIdx.x;
    if (gid < N_PTS) {
        float x = tgt[3 * gid], y = tgt[3 * gid + 1], z = tgt[3 * gid + 2];
        bool valid = (x != 0.0f) || (y != 0.0f) || (z != 0.0f);
        float t2 = fmaf(x, x, fmaf(y, y, z * z));
        float4 v;
        if (valid) { v.x = -2.0f * x; v.y = -2.0f * y; v.z = -2.0f * z; v.w = t2; }
        else       { v.x = 0.0f;      v.y = 0.0f;      v.z = 0.0f;      v.w = 1e30f; }
        int c = cell_coord(y) * NC + cell_coord(x);
        g_tsort[atomicAdd(&g_tcur[c], 1)] = v;
    } else {
        int i = gid - N_PTS;
        float x = src[3 * i], y = src[3 * i + 1], z = src[3 * i + 2];
        bool valid = (x != 0.0f) || (y != 0.0f) || (z != 0.0f);
        float s2 = fmaf(x, x, fmaf(y, y, z * z));
        float4 v; v.x = x; v.y = y; v.z = z; v.w = valid ? s2 : -1.0f;
        int c = cell_coord(y) * NC + cell_coord(x);
        g_ssort[atomicAdd(&g_scur[c], 1)] = v;
    }
}

// Branchless sorted insert, ascending m0..m4 (exact no-op when q >= m4).
__device__ __forceinline__ void insert5(float q, float& m0, float& m1,
                                        float& m2, float& m3, float& m4) {
    float t0 = fminf(m0, q);
    float t1 = fminf(m1, fmaxf(m0, q));
    float t2 = fminf(m2, fmaxf(m1, q));
    float t3 = fminf(m3, fmaxf(m2, q));
    float t4 = fminf(m4, fmaxf(m3, q));
    m0 = t0; m1 = t1; m2 = t2; m3 = t3; m4 = t4;
}

// Warp butterfly merge of 32 per-lane ascending-5 lists -> exact union top-5
// sorted ascending, identical on all lanes. (Validated in R4: rel_err = 0.)
__device__ __forceinline__ void warp_merge5(float& a0, float& a1, float& a2,
                                            float& a3, float& a4) {
#pragma unroll
    for (int off = 16; off > 0; off >>= 1) {
        float b0 = __shfl_xor_sync(0xffffffffu, a0, off);
        float b1 = __shfl_xor_sync(0xffffffffu, a1, off);
        float b2 = __shfl_xor_sync(0xffffffffu, a2, off);
        float b3 = __shfl_xor_sync(0xffffffffu, a3, off);
        float b4 = __shfl_xor_sync(0xffffffffu, a4, off);
        float c0 = fminf(a0, b4), c1 = fminf(a1, b3), c2 = fminf(a2, b2);
        float c3 = fminf(a3, b1), c4 = fminf(a4, b0);
        float l04 = fminf(c0, c4), h04 = fmaxf(c0, c4);
        float l13 = fminf(c1, c3), h13 = fmaxf(c1, c3);
        float l2h = fminf(c2, h04), h2h = fmaxf(c2, h04);
        a0 = l04;
        a1 = fminf(l13, l2h); a2 = fmaxf(l13, l2h);
        a3 = fminf(h13, h2h); a4 = fmaxf(h13, h2h);
    }
}

// ---------------------------------------------------------------------------
// Main: warp owns 4 cell-adjacent sources, per-lane branchless top-5,
// expanding square rings. Pruning bound per ring = EXACT union 5th
// (butterfly merge on copies) -> finite after just 5 candidates.
// ---------------------------------------------------------------------------
__global__ __launch_bounds__(MAIN_THREADS)
void knn_main() {
    __shared__ float red_s[MAIN_WARPS];
    __shared__ int   red_c[MAIN_WARPS];

    const int lane = threadIdx.x & 31;
    const int warp = threadIdx.x >> 5;
    const int sbase = (blockIdx.x * MAIN_WARPS + warp) * SRC_PER_WARP;

    float sx[SRC_PER_WARP], sy[SRC_PER_WARP], sz[SRC_PER_WARP], s2v[SRC_PER_WARP];
    bool  sval[SRC_PER_WARP];
    float xlo = 1e30f, xhi = -1e30f, ylo = 1e30f, yhi = -1e30f;
    bool any_valid = false;
#pragma unroll
    for (int s = 0; s < SRC_PER_WARP; ++s) {
        float4 v = g_ssort[sbase + s];
        sx[s] = v.x; sy[s] = v.y; sz[s] = v.z;
        sval[s] = (v.w >= 0.0f);
        s2v[s]  = fmaxf(v.w, 0.0f);
        if (sval[s]) {
            any_valid = true;
            xlo = fminf(xlo, v.x); xhi = fmaxf(xhi, v.x);
            ylo = fminf(ylo, v.y); yhi = fmaxf(yhi, v.y);
        }
    }

    float m[SRC_PER_WARP][KNN];
#pragma unroll
    for (int s = 0; s < SRC_PER_WARP; ++s)
#pragma unroll
        for (int k = 0; k < KNN; ++k) m[s][k] = 1e20f;

    if (any_valid) {
        // clamp bbox into grid domain (conservative for pruning bounds)
        float cxlo = fminf(fmaxf(xlo, XMIN), XMIN + NC * W);
        float cxhi = fminf(fmaxf(xhi, XMIN), XMIN + NC * W);
        float cylo = fminf(fmaxf(ylo, XMIN), XMIN + NC * W);
        float cyhi = fminf(fmaxf(yhi, XMIN), XMIN + NC * W);

        const int cx0 = cell_coord(cxlo), cx1 = cell_coord(cxhi);
        const int cy0 = cell_coord(cylo), cy1 = cell_coord(cyhi);

        float r2 = 1e30f;

        auto process_span = [&](int cy, int cxl, int cxr) {
            cxl = max(cxl, 0); cxr = min(cxr, NC - 1);
            if (cxl > cxr) return;
            int st = g_tstart[cy * NC + cxl];
            int en = g_tstart[cy * NC + cxr + 1];
            for (int i0 = st; i0 < en; i0 += 32) {
                int i = i0 + lane;
                float4 v = make_float4(0.0f, 0.0f, 0.0f, 1e30f);
                if (i < en) v = g_tsort[i];
#pragma unroll
                for (int s = 0; s < SRC_PER_WARP; ++s) {
                    float q = fmaf(sx[s], v.x,
                              fmaf(sy[s], v.y,
                              fmaf(sz[s], v.z, v.w)));
                    insert5(q, m[s][0], m[s][1], m[s][2], m[s][3], m[s][4]);
                }
            }
        };

        // home rect
        for (int cy = cy0; cy <= cy1; ++cy) process_span(cy, cx0, cx1);

        for (int rho = 1; rho < NC; ++rho) {
            // EXACT union-5th pruning bound (finite after only 5 candidates)
            float nr2 = 0.0f;
#pragma unroll
            for (int s = 0; s < SRC_PER_WARP; ++s) {
                float a0 = m[s][0], a1 = m[s][1], a2 = m[s][2],
                      a3 = m[s][3], a4 = m[s][4];
                warp_merge5(a0, a1, a2, a3, a4);
                if (sval[s]) nr2 = fmaxf(nr2, a4 + s2v[s]);
            }
            r2 = nr2;

            float lbr = (rho - 1) * W;
            if (lbr * lbr > r2) break;

            const int nx0 = cx0 - rho, nx1 = cx1 + rho;
            const int ny0 = cy0 - rho, ny1 = cy1 + rho;

            if (ny0 >= 0) {
                float dy = fmaxf(cylo - (XMIN + (ny0 + 1) * W), 0.0f);
                if (dy * dy <= r2) process_span(ny0, nx0, nx1);
            }
            if (ny1 <= NC - 1) {
                float dy = fmaxf((XMIN + ny1 * W) - cyhi, 0.0f);
                if (dy * dy <= r2) process_span(ny1, nx0, nx1);
            }
            int ra = max(ny0 + 1, 0), rb = min(ny1 - 1, NC - 1);
            if (nx0 >= 0) {
                float dx = fmaxf(cxlo - (XMIN + (nx0 + 1) * W), 0.0f);
                if (dx * dx <= r2) {
                    for (int r = ra; r <= rb; ++r) {
                        float cymin = XMIN + r * W;
                        float dy = fmaxf(fmaxf(cymin - cyhi, cylo - (cymin + W)), 0.0f);
                        if (fmaf(dy, dy, dx * dx) <= r2) process_span(r, nx0, nx0);
                    }
                }
            }
            if (nx1 <= NC - 1) {
                float dx = fmaxf((XMIN + nx1 * W) - cxhi, 0.0f);
                if (dx * dx <= r2) {
                    for (int r = ra; r <= rb; ++r) {
                        float cymin = XMIN + r * W;
                        float dy = fmaxf(fmaxf(cymin - cyhi, cylo - (cymin + W)), 0.0f);
                        if (fmaf(dy, dy, dx * dx) <= r2) process_span(r, nx1, nx1);
                    }
                }
            }
            if (nx0 <= 0 && nx1 >= NC - 1 && ny0 <= 0 && ny1 >= NC - 1) break;
        }
    }

    // final exact merge + loss contribution
    float wsum = 0.0f; int wcnt = 0;
#pragma unroll
    for (int s = 0; s < SRC_PER_WARP; ++s) {
        float a0 = m[s][0], a1 = m[s][1], a2 = m[s][2], a3 = m[s][3], a4 = m[s][4];
        warp_merge5(a0, a1, a2, a3, a4);
        float acc = sqrtf(fmaxf(a0 + s2v[s], 1e-12f))
                  + sqrtf(fmaxf(a1 + s2v[s], 1e-12f))
                  + sqrtf(fmaxf(a2 + s2v[s], 1e-12f))
                  + sqrtf(fmaxf(a3 + s2v[s], 1e-12f))
                  + sqrtf(fmaxf(a4 + s2v[s], 1e-12f));
        if (sval[s]) { wsum += acc; wcnt += 1; }
    }

    if (lane == 0) { red_s[warp] = wsum; red_c[warp] = wcnt; }
    __syncthreads();
    if (threadIdx.x == 0) {
        float bs = 0.0f; int bc = 0;
#pragma unroll
        for (int w = 0; w < MAIN_WARPS; ++w) { bs += red_s[w]; bc += red_c[w]; }
        g_bsum[blockIdx.x] = bs;
        g_bcnt[blockIdx.x] = bc;
    }
}

// ---------------------------------------------------------------------------
__global__ void finalize_kernel(float* __restrict__ out) {
    __shared__ double ds[256];
    __shared__ int    di[256];
    int tid = threadIdx.x;
    double s = 0.0; int c = 0;
    for (int i = tid; i < MAIN_BLOCKS; i += 256) { s += (double)g_bsum[i]; c += g_bcnt[i]; }
    ds[tid] = s; di[tid] = c;
    __syncthreads();
#pragma unroll
    for (int off = 128; off > 0; off >>= 1) {
        if (tid < off) { ds[tid] += ds[tid + off]; di[tid] += di[tid + off]; }
        __syncthreads();
    }
    if (tid == 0) out[0] = (float)(ds[0] / ((double)di[0] * KNN));
    // re-zero histograms for next call (first call uses load-time zero-init)
    for (int i = tid; i < NCELLS; i += 256) { g_thist[i] = 0; g_shist[i] = 0; }
}

// ---------------------------------------------------------------------------
extern "C" void kernel_launch(void* const* d_in, const int* in_sizes, int n_in,
                              void* d_out, int out_size) {
    const float* src = (const float*)d_in[0];  // source_pc (2,8192,3)
    const float* tgt = (const float*)d_in[1];  // target_pc (2,8192,3)
    float* out = (float*)d_out;

    hist_kernel<<<2 * N_PTS / 256, 256>>>(src, tgt);     // launch 0
    scan_kernel<<<1, 1024>>>();                          // launch 1
    scatter_kernel<<<2 * N_PTS / 256, 256>>>(src, tgt);  // launch 2
    knn_main<<<MAIN_BLOCKS, MAIN_THREADS>>>();           // launch 3
    finalize_kernel<<<1, 256>>>(out);                    // launch 4
}